// round 10
// baseline (speedup 1.0000x reference)
#include <cuda_runtime.h>

// SWT db4, 3 levels, wrap. x:(64,32,4096) f32 -> out:(64,32,4096,4) = [a3,d3,d2,d1].
// out[t] = sum_j f[j] * in[(t + (4-j)*dil) mod 4096], dil = 1,2,4.
//
// R10: pass1/pass2 vectorized granule windows (as R9).  lo2, d1, d2 are staged
// PHASE-DEINTERLEAVED (dil=4 conv == 4 independent dil=1 convs of length 1024),
// so pass3 reads 3 aligned LDS.128 per 4 outputs (12 B/elem vs 32) and d1/d2
// readback is one aligned LDS.128 per 4 outputs.

#define SWT_T   4096
#define SWT_G   1024
#define SWT_NT  512

// float offsets inside dynamic SMEM
#define A_F4     1040                 // region A: 1040 float4 = 4160 floats
#define X_CORE   1                    // x granule core offset (granules)
#define B_F4     1029                 // region B: lo1 granules
#define B_CORE   2
#define PH_STRIDE 1040                // floats per phase array (4 left halo + 1024 + 8 right + pad)
#define OFF_B    (A_F4 * 4)           // 4160
#define OFF_D2   (OFF_B + B_F4 * 4)   // 8276
#define OFF_D1   (OFF_D2 + 4 * SWT_G) // 12372
#define SMEM_FLOATS (OFF_D1 + 4 * SWT_G)      // 16468
#define SMEM_BYTES  (SMEM_FLOATS * 4)         // 65872

__global__ __launch_bounds__(SWT_NT, 3)
void swt_db4_l3_kernel(const float* __restrict__ x,
                       const float* __restrict__ dec_lo,
                       const float* __restrict__ dec_hi,
                       float4* __restrict__ out)
{
    extern __shared__ float smem_f[];
    float4* s_a   = reinterpret_cast<float4*>(smem_f);            // x, later phases overlay
    float4* s_b   = reinterpret_cast<float4*>(smem_f + OFF_B);    // lo1
    float*  s_ph  = smem_f;                                       // phase arrays (overlay A)
    float*  s_d2p = smem_f + OFF_D2;                              // [4][1024]
    float*  s_d1p = smem_f + OFF_D1;                              // [4][1024]

    const int row = blockIdx.x;
    const int tid = threadIdx.x;

    float flo[8], fhi[8];
#pragma unroll
    for (int j = 0; j < 8; ++j) {
        flo[j] = __ldg(&dec_lo[j]);
        fhi[j] = __ldg(&dec_hi[j]);
    }

    // ---- Load x row + wrap halos (granules [-1, 1026) around core) ----
    const float4* xr4 = reinterpret_cast<const float4*>(x + (size_t)row * SWT_T);
#pragma unroll
    for (int s = 0; s < 2; ++s) {
        const int g = tid + s * SWT_NT;
        float4 v = xr4[g];
        s_a[X_CORE + g] = v;
        if (g == SWT_G - 1) s_a[0] = v;                      // left halo: x[4092..)
        if (g < 2)          s_a[X_CORE + SWT_G + g] = v;     // right halo: x[0..8)
    }
    __syncthreads();

    // ---- Pass 1 (dil=1): lo1 -> s_b (+halos), d1 -> phase staging.
    //      Window [t0-4, t0+8) = x granules g-1..g+1. ----
#pragma unroll
    for (int s = 0; s < 2; ++s) {
        const int g = tid + s * SWT_NT;          // t0 = 4g
        float lo1[4] = {0.f, 0.f, 0.f, 0.f};
        float hi1[4] = {0.f, 0.f, 0.f, 0.f};
#pragma unroll
        for (int i = 0; i < 3; ++i) {
            const float4 w = s_a[g + i];         // x granule g-1+i
            const float wv[4] = {w.x, w.y, w.z, w.w};
#pragma unroll
            for (int p = 0; p < 4; ++p) {
                const int o = 4 * i - 4 + p;
#pragma unroll
                for (int c = 0; c < 4; ++c) {
                    const int j = 4 - o + c;     // o = c + (4-j)
                    if (j >= 0 && j <= 7) {
                        lo1[c] = fmaf(flo[j], wv[p], lo1[c]);
                        hi1[c] = fmaf(fhi[j], wv[p], hi1[c]);
                    }
                }
            }
        }
        const float4 v = make_float4(lo1[0], lo1[1], lo1[2], lo1[3]);
        s_b[B_CORE + g] = v;
        if (g >= SWT_G - 2) s_b[B_CORE + g - SWT_G] = v;      // left halo (2)
        if (g < 2)          s_b[B_CORE + SWT_G + g] = v;      // right halo (2)
#pragma unroll
        for (int c = 0; c < 4; ++c)
            s_d1p[c * SWT_G + g] = hi1[c];                    // phase-deinterleaved
    }
    __syncthreads();   // all p1 reads of s_a(x) retired; phases may overlay A

    // ---- Pass 2 (dil=2): phases(lo2) -> s_ph (+halos), d2 -> phase staging.
    //      Window [t0-8, t0+12) = lo1 granules g-2..g+2. ----
#pragma unroll
    for (int s = 0; s < 2; ++s) {
        const int g = tid + s * SWT_NT;
        float lo2[4] = {0.f, 0.f, 0.f, 0.f};
        float hi2[4] = {0.f, 0.f, 0.f, 0.f};
#pragma unroll
        for (int i = 0; i < 5; ++i) {
            const float4 w = s_b[g + i];         // lo1 granule g-2+i
            const float wv[4] = {w.x, w.y, w.z, w.w};
#pragma unroll
            for (int p = 0; p < 4; ++p) {
                const int o = 4 * i - 8 + p;
#pragma unroll
                for (int c = (o & 1); c < 4; c += 2) {
                    const int j = 4 - (o - c) / 2;   // o = c + 2(4-j)
                    if (j >= 0 && j <= 7) {
                        lo2[c] = fmaf(flo[j], wv[p], lo2[c]);
                        hi2[c] = fmaf(fhi[j], wv[p], hi2[c]);
                    }
                }
            }
        }
        // lo2[c] = lo2 at t = 4g+c  ->  phase c, position g.  Halos: [-3,0)+[1024,1031)
#pragma unroll
        for (int c = 0; c < 4; ++c) {
            float* ph = s_ph + c * PH_STRIDE + 4;
            ph[g] = lo2[c];
            if (g >= SWT_G - 3) ph[g - SWT_G] = lo2[c];
            if (g < 7)          ph[g + SWT_G] = lo2[c];
            s_d2p[c * SWT_G + g] = hi2[c];
        }
    }
    __syncthreads();

    // ---- Pass 3 (dil=1 in phase space): a3/d3 from phases, merge d2/d1, write out.
    //      out3[4q+c] = sum_j f[j] * phase[c][q+4-j].  Thread: phase c = tid&3,
    //      4 consecutive q starting q0 = (tid>>2)*4 + r*512. ----
    float4* out_row = out + (size_t)row * SWT_T;
    const int c  = tid & 3;
    const int qb = tid >> 2;
    const float* ph  = s_ph + c * PH_STRIDE + 4;
    const float* d1p = s_d1p + c * SWT_G;
    const float* d2p = s_d2p + c * SWT_G;
#pragma unroll
    for (int r = 0; r < 2; ++r) {
        const int q0 = qb * 4 + r * (SWT_T / 8);   // 0..1020 step 4
        const float4 w0 = *reinterpret_cast<const float4*>(ph + q0 - 4);
        const float4 w1 = *reinterpret_cast<const float4*>(ph + q0);
        const float4 w2 = *reinterpret_cast<const float4*>(ph + q0 + 4);
        const float win[12] = {w0.x, w0.y, w0.z, w0.w,
                               w1.x, w1.y, w1.z, w1.w,
                               w2.x, w2.y, w2.z, w2.w};
        const float4 d1v = *reinterpret_cast<const float4*>(d1p + q0);
        const float4 d2v = *reinterpret_cast<const float4*>(d2p + q0);
        const float d1a[4] = {d1v.x, d1v.y, d1v.z, d1v.w};
        const float d2a[4] = {d2v.x, d2v.y, d2v.z, d2v.w};
#pragma unroll
        for (int u = 0; u < 4; ++u) {
            float a3 = 0.f, d3 = 0.f;
#pragma unroll
            for (int j = 0; j < 8; ++j) {
                const float v = win[u + 8 - j];    // phase[c][q0+u+4-j]
                a3 = fmaf(flo[j], v, a3);
                d3 = fmaf(fhi[j], v, d3);
            }
            out_row[4 * (q0 + u) + c] = make_float4(a3, d3, d2a[u], d1a[u]);
        }
    }
}

extern "C" void kernel_launch(void* const* d_in, const int* in_sizes, int n_in,
                              void* d_out, int out_size)
{
    const float* x      = (const float*)d_in[0];
    const float* dec_lo = (const float*)d_in[1];
    const float* dec_hi = (const float*)d_in[2];
    float4* out         = (float4*)d_out;

    cudaFuncSetAttribute(swt_db4_l3_kernel,
                         cudaFuncAttributeMaxDynamicSharedMemorySize, SMEM_BYTES);

    const int rows = in_sizes[0] / SWT_T;   // 2048
    swt_db4_l3_kernel<<<rows, SWT_NT, SMEM_BYTES>>>(x, dec_lo, dec_hi, out);
}

// round 12
// speedup vs baseline: 1.1453x; 1.1453x over previous
#include <cuda_runtime.h>

// SWT db4, 3 levels, wrap. x:(64,32,4096) f32 -> out:(64,32,4096,4) = [a3,d3,d2,d1].
// out[t] = sum_j f[j] * in[(t + (4-j)*dil) mod 4096], dil = 1,2,4.
//
// R11 = R10 (phase-deinterleaved level 3) + bank-conflict-free strides:
//   phase arrays stride 1048 floats (== 24 mod 32 banks),
//   d1/d2 staging stride 1032 floats (==  8 mod 32 banks),
// making every pass-3 LDS.128 8-lane phase hit 8 disjoint 4-bank windows.

#define SWT_T   4096
#define SWT_G   1024
#define SWT_NT  512

#define X_CORE    1                   // x granule core offset (granules)
#define B_CORE    2                   // lo1 granule core offset
#define PH_STRIDE 1048                // floats per lo2-phase array  (24 mod 32)
#define D_STRIDE  1032                // floats per d1/d2 phase array ( 8 mod 32)

#define OFF_B    4192                 // floats: after phase region (4*1048)
#define OFF_D2   (OFF_B + 1029 * 4)   // 8308
#define OFF_D1   (OFF_D2 + 4 * D_STRIDE)      // 12436
#define SMEM_FLOATS (OFF_D1 + 4 * D_STRIDE)   // 16564
#define SMEM_BYTES  (SMEM_FLOATS * 4)         // 66256

__global__ __launch_bounds__(SWT_NT, 3)
void swt_db4_l3_kernel(const float* __restrict__ x,
                       const float* __restrict__ dec_lo,
                       const float* __restrict__ dec_hi,
                       float4* __restrict__ out)
{
    extern __shared__ float smem_f[];
    float4* s_a   = reinterpret_cast<float4*>(smem_f);            // x (overlaid by phases)
    float4* s_b   = reinterpret_cast<float4*>(smem_f + OFF_B);    // lo1
    float*  s_ph  = smem_f;                                       // 4 lo2-phase arrays
    float*  s_d2p = smem_f + OFF_D2;                              // 4 d2-phase arrays
    float*  s_d1p = smem_f + OFF_D1;                              // 4 d1-phase arrays

    const int row = blockIdx.x;
    const int tid = threadIdx.x;

    float flo[8], fhi[8];
#pragma unroll
    for (int j = 0; j < 8; ++j) {
        flo[j] = __ldg(&dec_lo[j]);
        fhi[j] = __ldg(&dec_hi[j]);
    }

    // ---- Load x row + wrap halos (granules [-1, 1026) around core) ----
    const float4* xr4 = reinterpret_cast<const float4*>(x + (size_t)row * SWT_T);
#pragma unroll
    for (int s = 0; s < 2; ++s) {
        const int g = tid + s * SWT_NT;
        float4 v = xr4[g];
        s_a[X_CORE + g] = v;
        if (g == SWT_G - 1) s_a[0] = v;                      // left halo: x[4092..)
        if (g < 2)          s_a[X_CORE + SWT_G + g] = v;     // right halo: x[0..8)
    }
    __syncthreads();

    // ---- Pass 1 (dil=1): lo1 -> s_b (+halos), d1 -> phase staging.
    //      Window [t0-4, t0+8) = x granules g-1..g+1. ----
#pragma unroll
    for (int s = 0; s < 2; ++s) {
        const int g = tid + s * SWT_NT;          // t0 = 4g
        float lo1[4] = {0.f, 0.f, 0.f, 0.f};
        float hi1[4] = {0.f, 0.f, 0.f, 0.f};
#pragma unroll
        for (int i = 0; i < 3; ++i) {
            const float4 w = s_a[g + i];         // x granule g-1+i
            const float wv[4] = {w.x, w.y, w.z, w.w};
#pragma unroll
            for (int p = 0; p < 4; ++p) {
                const int o = 4 * i - 4 + p;
#pragma unroll
                for (int c = 0; c < 4; ++c) {
                    const int j = 4 - o + c;     // o = c + (4-j)
                    if (j >= 0 && j <= 7) {
                        lo1[c] = fmaf(flo[j], wv[p], lo1[c]);
                        hi1[c] = fmaf(fhi[j], wv[p], hi1[c]);
                    }
                }
            }
        }
        const float4 v = make_float4(lo1[0], lo1[1], lo1[2], lo1[3]);
        s_b[B_CORE + g] = v;
        if (g >= SWT_G - 2) s_b[B_CORE + g - SWT_G] = v;      // left halo (2)
        if (g < 2)          s_b[B_CORE + SWT_G + g] = v;      // right halo (2)
#pragma unroll
        for (int c = 0; c < 4; ++c)
            s_d1p[c * D_STRIDE + g] = hi1[c];                 // phase-deinterleaved
    }
    __syncthreads();   // all p1 reads of s_a(x) retired; phases may overlay A

    // ---- Pass 2 (dil=2): lo2 phases -> s_ph (+halos), d2 -> phase staging.
    //      Window [t0-8, t0+12) = lo1 granules g-2..g+2. ----
#pragma unroll
    for (int s = 0; s < 2; ++s) {
        const int g = tid + s * SWT_NT;
        float lo2[4] = {0.f, 0.f, 0.f, 0.f};
        float hi2[4] = {0.f, 0.f, 0.f, 0.f};
#pragma unroll
        for (int i = 0; i < 5; ++i) {
            const float4 w = s_b[g + i];         // lo1 granule g-2+i
            const float wv[4] = {w.x, w.y, w.z, w.w};
#pragma unroll
            for (int p = 0; p < 4; ++p) {
                const int o = 4 * i - 8 + p;
#pragma unroll
                for (int c = (o & 1); c < 4; c += 2) {
                    const int j = 4 - (o - c) / 2;   // o = c + 2(4-j)
                    if (j >= 0 && j <= 7) {
                        lo2[c] = fmaf(flo[j], wv[p], lo2[c]);
                        hi2[c] = fmaf(fhi[j], wv[p], hi2[c]);
                    }
                }
            }
        }
        // lo2[c] at t = 4g+c -> phase c, position g. Halos: [-3,0) and [1024,1031)
#pragma unroll
        for (int c = 0; c < 4; ++c) {
            float* ph = s_ph + c * PH_STRIDE + 4;
            ph[g] = lo2[c];
            if (g >= SWT_G - 3) ph[g - SWT_G] = lo2[c];
            if (g < 7)          ph[g + SWT_G] = lo2[c];
            s_d2p[c * D_STRIDE + g] = hi2[c];
        }
    }
    __syncthreads();

    // ---- Pass 3 (dil=1 in phase space): a3/d3 from phases, merge d2/d1.
    //      out3[4q+c] = sum_j f[j] * phase[c][q+4-j].
    //      Thread: phase c = tid&3, 4 consecutive q from q0 = (tid>>2)*4 + r*512. ----
    float4* out_row = out + (size_t)row * SWT_T;
    const int c  = tid & 3;
    const int qb = tid >> 2;
    const float* ph  = s_ph + c * PH_STRIDE + 4;
    const float* d1p = s_d1p + c * D_STRIDE;
    const float* d2p = s_d2p + c * D_STRIDE;
#pragma unroll
    for (int r = 0; r < 2; ++r) {
        const int q0 = qb * 4 + r * (SWT_T / 8);   // 0..1020 step 4
        const float4 w0 = *reinterpret_cast<const float4*>(ph + q0 - 4);
        const float4 w1 = *reinterpret_cast<const float4*>(ph + q0);
        const float4 w2 = *reinterpret_cast<const float4*>(ph + q0 + 4);
        const float win[12] = {w0.x, w0.y, w0.z, w0.w,
                               w1.x, w1.y, w1.z, w1.w,
                               w2.x, w2.y, w2.z, w2.w};
        const float4 d1v = *reinterpret_cast<const float4*>(d1p + q0);
        const float4 d2v = *reinterpret_cast<const float4*>(d2p + q0);
        const float d1a[4] = {d1v.x, d1v.y, d1v.z, d1v.w};
        const float d2a[4] = {d2v.x, d2v.y, d2v.z, d2v.w};
#pragma unroll
        for (int u = 0; u < 4; ++u) {
            float a3 = 0.f, d3 = 0.f;
#pragma unroll
            for (int j = 0; j < 8; ++j) {
                const float v = win[u + 8 - j];    // phase[c][q0+u+4-j]
                a3 = fmaf(flo[j], v, a3);
                d3 = fmaf(fhi[j], v, d3);
            }
            out_row[4 * (q0 + u) + c] = make_float4(a3, d3, d2a[u], d1a[u]);
        }
    }
}

extern "C" void kernel_launch(void* const* d_in, const int* in_sizes, int n_in,
                              void* d_out, int out_size)
{
    const float* x      = (const float*)d_in[0];
    const float* dec_lo = (const float*)d_in[1];
    const float* dec_hi = (const float*)d_in[2];
    float4* out         = (float4*)d_out;

    cudaFuncSetAttribute(swt_db4_l3_kernel,
                         cudaFuncAttributeMaxDynamicSharedMemorySize, SMEM_BYTES);

    const int rows = in_sizes[0] / SWT_T;   // 2048
    swt_db4_l3_kernel<<<rows, SWT_NT, SMEM_BYTES>>>(x, dec_lo, dec_hi, out);
}